// round 2
// baseline (speedup 1.0000x reference)
#include <cuda_runtime.h>
#include <cuda_bf16.h>

// Problem: B=512, S=512, I=64, C=4, H=100, O=7
// out = [output (512*7)] ++ [hidden_states (512*512*100)]

#define ULL unsigned long long

// ---------------- scratch (device globals; no runtime allocation) -----------
__device__ float g_xf[512 * 512 * 100];
__device__ float g_xh[512 * 512 * 100];

// ---------------- helpers ---------------------------------------------------
__device__ __forceinline__ ULL fma2(ULL a, ULL b, ULL c) {
    ULL d;
    asm("fma.rn.f32x2 %0, %1, %2, %3;" : "=l"(d) : "l"(a), "l"(b), "l"(c));
    return d;
}
__device__ __forceinline__ float hsum2(ULL a) {
    float lo, hi;
    asm("mov.b64 {%0,%1}, %2;" : "=f"(lo), "=f"(hi) : "l"(a));
    return lo + hi;
}
__device__ __forceinline__ float sigmoidf_(float v) {
    return __fdividef(1.f, 1.f + __expf(-v));
}
__device__ __forceinline__ float tanhf_(float v) {
    // stable: x->+inf => exp->inf => 1 - 0 = 1 ; x->-inf => exp->0 => -1
    return 1.f - __fdividef(2.f, __expf(2.f * v) + 1.f);
}

// ---------------- K1: xf/xh precompute (262144 x 200 x 64 GEMM + ctx bias) --
__global__ void __launch_bounds__(256, 2)
pre_kernel(const float* __restrict__ x, const float* __restrict__ ctx,
           const float* __restrict__ Wf_w, const float* __restrict__ Wf_b,
           const float* __restrict__ Wh_w, const float* __restrict__ Wh_b)
{
    __shared__ __align__(16) ULL sh_w[100][2][32];  // [j][gate][k-pair], 51.2KB
    __shared__ float sh_cb[2][100];                 // ctx-folded bias

    const int tid = threadIdx.x;

    // cooperative weight load (k-pairs of first 64 columns; 8B-aligned: 168j even)
    for (int idx = tid; idx < 6400; idx += 256) {
        int j = idx >> 6, rem = idx & 63, g = rem >> 5, kk = rem & 31;
        const float* W = g ? Wh_w : Wf_w;
        sh_w[j][g][kk] = *(const ULL*)(W + j * 168 + 2 * kk);
    }
    if (tid < 200) {
        int g = tid / 100, j = tid % 100;
        const float* W = g ? Wh_w : Wf_w;
        const float* Bb = g ? Wh_b : Wf_b;
        float cb = Bb[j];
        #pragma unroll
        for (int cc = 0; cc < 4; cc++) cb += ctx[cc] * W[j * 168 + 64 + cc];
        sh_cb[g][j] = cb;
    }
    __syncthreads();

    const size_t p = (size_t)blockIdx.x * 256 + tid;  // position (b*512+s)

    // x row -> registers, k-pair packed
    ULL xv[32];
    const ulonglong2* xp = (const ulonglong2*)(x + p * 64);
    #pragma unroll
    for (int g = 0; g < 16; g++) { ulonglong2 v = xp[g]; xv[2 * g] = v.x; xv[2 * g + 1] = v.y; }

    float* of = g_xf + p * 100;
    float* oh = g_xh + p * 100;

    #pragma unroll 2
    for (int j = 0; j < 100; j++) {
        ULL af = 0ull, ah = 0ull;
        const ulonglong2* wf = (const ulonglong2*)&sh_w[j][0][0];
        const ulonglong2* wh = (const ulonglong2*)&sh_w[j][1][0];
        #pragma unroll
        for (int g = 0; g < 16; g++) {
            ulonglong2 a = wf[g];
            ulonglong2 b2 = wh[g];
            af = fma2(a.x, xv[2 * g], af);
            ah = fma2(b2.x, xv[2 * g], ah);
            af = fma2(a.y, xv[2 * g + 1], af);
            ah = fma2(b2.y, xv[2 * g + 1], ah);
        }
        of[j] = hsum2(af) + sh_cb[0][j];
        oh[j] = hsum2(ah) + sh_cb[1][j];
    }
}

// ---------------- K2: sequential scan ---------------------------------------
// 128 blocks x 4 batch rows. 200 threads: c=tid/100 (k-chunk), j=tid%100.
// chunk c0: k in [0,52) (13 quad-groups, 26 pair-weights)
// chunk c1: k in [52,104) (13 quad-groups, 24 real pair-weights + 2 zeros;
//           k 100..103 is zero padding in shared)
__device__ __forceinline__ void matvec_part(const float (*shm)[104], const ULL* w2,
                                            int kb, float out[4])
{
    ULL a0 = 0ull, a1 = 0ull, a2 = 0ull, a3 = 0ull;
    #pragma unroll
    for (int g = 0; g < 13; g++) {
        ulonglong2 h0 = *(const ulonglong2*)&shm[0][kb + 4 * g];
        ulonglong2 h1 = *(const ulonglong2*)&shm[1][kb + 4 * g];
        ulonglong2 h2 = *(const ulonglong2*)&shm[2][kb + 4 * g];
        ulonglong2 h3 = *(const ulonglong2*)&shm[3][kb + 4 * g];
        a0 = fma2(w2[2 * g], h0.x, a0); a0 = fma2(w2[2 * g + 1], h0.y, a0);
        a1 = fma2(w2[2 * g], h1.x, a1); a1 = fma2(w2[2 * g + 1], h1.y, a1);
        a2 = fma2(w2[2 * g], h2.x, a2); a2 = fma2(w2[2 * g + 1], h2.y, a2);
        a3 = fma2(w2[2 * g], h3.x, a3); a3 = fma2(w2[2 * g + 1], h3.y, a3);
    }
    out[0] = hsum2(a0); out[1] = hsum2(a1); out[2] = hsum2(a2); out[3] = hsum2(a3);
}

__global__ void __launch_bounds__(200, 1)
scan_kernel(const float* __restrict__ Wf_w, const float* __restrict__ Wh_w,
            float* __restrict__ hidden)
{
    const int tid = threadIdx.x;
    const int c = tid / 100;   // 0 or 1
    const int j = tid % 100;
    const int rbase = blockIdx.x * 4;

    __shared__ __align__(16) float sh_h[4][104];
    __shared__ __align__(16) float sh_fh[4][104];
    __shared__ __align__(16) float4 sh_part1[100];  // c1 partials

    const int kb = c ? 52 : 0;
    const int lc = c ? 24 : 26;  // real pair-weights in this chunk

    // recurrence weights: W*_w[j][68 + k], k-pair packed, register-resident
    ULL wf2[26], wh2[26];
    {
        const ULL* pf = (const ULL*)(Wf_w + j * 168 + 68 + kb);
        const ULL* ph = (const ULL*)(Wh_w + j * 168 + 68 + kb);
        #pragma unroll
        for (int t = 0; t < 26; t++) {
            if (t < lc) { wf2[t] = pf[t]; wh2[t] = ph[t]; }
            else        { wf2[t] = 0ull;  wh2[t] = 0ull; }
        }
    }

    // h0 = 0 (also zeroes the k=100..103 padding, which must stay finite)
    for (int idx = tid; idx < 4 * 104; idx += 200) {
        (&sh_h[0][0])[idx]  = 0.f;
        (&sh_fh[0][0])[idx] = 0.f;
    }
    __syncthreads();

    // prefetched gate pre-activations (c0 threads only)
    float xfc[4], xhc[4], fgate[4], hold[4];
    if (c == 0) {
        #pragma unroll
        for (int r = 0; r < 4; r++) {
            size_t b0 = (size_t)(rbase + r) * 51200 + j;  // s = 0
            xfc[r] = g_xf[b0];
            xhc[r] = g_xh[b0];
        }
    }

    #pragma unroll 1
    for (int s = 0; s < 512; s++) {
        // -- matvec 1: Wf_h . h (partial over own chunk)
        float pf[4];
        matvec_part(sh_h, wf2, kb, pf);
        if (c == 1) sh_part1[j] = make_float4(pf[0], pf[1], pf[2], pf[3]);
        __syncthreads();  // (1)

        if (c == 0) {
            float4 o = sh_part1[j];
            float ov[4] = {o.x, o.y, o.z, o.w};
            #pragma unroll
            for (int r = 0; r < 4; r++) {
                fgate[r] = sigmoidf_(pf[r] + ov[r] + xfc[r]);
                hold[r]  = sh_h[r][j];
                sh_fh[r][j] = fgate[r] * hold[r];
            }
        }
        __syncthreads();  // (2)

        // -- matvec 2: Wh_h . (f*h)
        float qh[4];
        matvec_part(sh_fh, wh2, kb, qh);
        if (c == 1) sh_part1[j] = make_float4(qh[0], qh[1], qh[2], qh[3]);
        __syncthreads();  // (3)

        if (c == 0) {
            float4 o = sh_part1[j];
            float ov[4] = {o.x, o.y, o.z, o.w};
            #pragma unroll
            for (int r = 0; r < 4; r++) {
                float ht = tanhf_(qh[r] + ov[r] + xhc[r]);
                float hn = hold[r] + fgate[r] * (ht - hold[r]);
                sh_h[r][j] = hn;
                hidden[((size_t)(rbase + r) * 512 + s) * 100 + j] = hn;
            }
            // prefetch next step's pre-activations
            int sp = (s + 1 < 512) ? (s + 1) : 511;
            #pragma unroll
            for (int r = 0; r < 4; r++) {
                size_t b0 = (size_t)(rbase + r) * 51200 + (size_t)sp * 100 + j;
                xfc[r] = g_xf[b0];
                xhc[r] = g_xh[b0];
            }
        }
        __syncthreads();  // (4)
    }
}

// ---------------- K3: output head -------------------------------------------
__global__ void head_kernel(const float* __restrict__ hidden,
                            const float* __restrict__ ro_w,
                            const float* __restrict__ ro_b,
                            float* __restrict__ out)
{
    int t = blockIdx.x * blockDim.x + threadIdx.x;
    if (t >= 512 * 7) return;
    int b = t / 7, o = t % 7;
    const float* h = hidden + ((size_t)b * 512 + 511) * 100;
    const float* w = ro_w + o * 100;
    float acc = ro_b[o];
    #pragma unroll 4
    for (int k = 0; k < 100; k++) acc += h[k] * w[k];
    out[t] = acc;
}

// ---------------- launch -----------------------------------------------------
extern "C" void kernel_launch(void* const* d_in, const int* in_sizes, int n_in,
                              void* d_out, int out_size)
{
    (void)in_sizes; (void)n_in; (void)out_size;
    const float* x     = (const float*)d_in[0];
    const float* ctx   = (const float*)d_in[1];
    const float* Wf_w  = (const float*)d_in[2];
    const float* Wf_b  = (const float*)d_in[3];
    const float* Wh_w  = (const float*)d_in[4];
    const float* Wh_b  = (const float*)d_in[5];
    const float* ro_w  = (const float*)d_in[6];
    const float* ro_b  = (const float*)d_in[7];

    float* out    = (float*)d_out;
    float* hidden = out + 512 * 7;

    pre_kernel<<<1024, 256>>>(x, ctx, Wf_w, Wf_b, Wh_w, Wh_b);
    scan_kernel<<<128, 200>>>(Wf_w, Wh_w, hidden);
    head_kernel<<<14, 256>>>(hidden, ro_w, ro_b, out);
}

// round 4
// speedup vs baseline: 1.2504x; 1.2504x over previous
#include <cuda_runtime.h>
#include <cuda_bf16.h>

// Problem: B=512, S=512, I=64, C=4, H=100, O=7
// out = [output (512*7)] ++ [hidden_states (512*512*100)]

#define ULL unsigned long long

// ---------------- scratch (device globals; no runtime allocation) -----------
__device__ float g_xf[512 * 512 * 100];
__device__ float g_xh[512 * 512 * 100];

// ---------------- helpers ---------------------------------------------------
__device__ __forceinline__ ULL fma2(ULL a, ULL b, ULL c) {
    ULL d;
    asm("fma.rn.f32x2 %0, %1, %2, %3;" : "=l"(d) : "l"(a), "l"(b), "l"(c));
    return d;
}
__device__ __forceinline__ float hsum2(ULL a) {
    float lo, hi;
    asm("mov.b64 {%0,%1}, %2;" : "=f"(lo), "=f"(hi) : "l"(a));
    return lo + hi;
}
__device__ __forceinline__ float sigmoidf_(float v) {
    return __fdividef(1.f, 1.f + __expf(-v));
}
__device__ __forceinline__ float tanhf_(float v) {
    return 1.f - __fdividef(2.f, __expf(2.f * v) + 1.f);
}

// ---------------- K1: xf/xh precompute --------------------------------------
// 1024 blocks x 256 threads, 1 position/thread, x in regs (k-pair packed),
// one gate's weights resident in shared at a time. Outputs staged through a
// shared transpose buffer in 16-j groups so global stores are coalesced
// (previous version's 400B-strided STG.32 was the wavefront bottleneck).
__global__ void __launch_bounds__(256, 2)
pre_kernel(const float* __restrict__ x, const float* __restrict__ ctx,
           const float* __restrict__ Wf_w, const float* __restrict__ Wf_b,
           const float* __restrict__ Wh_w, const float* __restrict__ Wh_b)
{
    __shared__ __align__(16) ULL sh_w[100][32];   // one gate: 25.6 KB
    __shared__ float sh_cb[100];                  // ctx-folded bias
    __shared__ __align__(16) float sh_t[256][17]; // transpose buffer (+1 pad)

    const int tid = threadIdx.x;
    const size_t p = (size_t)blockIdx.x * 256 + tid;  // position (b*512+s)

    // x row -> registers, k-pair packed (64 floats = 32 ULL)
    ULL xv[32];
    {
        const ulonglong2* xp = (const ulonglong2*)(x + p * 64);
        #pragma unroll
        for (int g = 0; g < 16; g++) {
            ulonglong2 v = xp[g];
            xv[2 * g] = v.x; xv[2 * g + 1] = v.y;
        }
    }

    #pragma unroll 1
    for (int gate = 0; gate < 2; gate++) {
        const float* W  = gate ? Wh_w : Wf_w;
        const float* Bb = gate ? Wh_b : Wf_b;
        float* dst_base = (gate ? g_xh : g_xf) + (size_t)blockIdx.x * 256 * 100;

        __syncthreads();  // protect sh_w / sh_t reuse across gates
        // load this gate's first-64-column weights, k-pair packed
        for (int idx = tid; idx < 3200; idx += 256) {
            int j = idx >> 5, kk = idx & 31;
            sh_w[j][kk] = *(const ULL*)(W + j * 168 + 2 * kk);
        }
        if (tid < 100) {
            float cb = Bb[tid];
            #pragma unroll
            for (int cc = 0; cc < 4; cc++) cb += ctx[cc] * W[tid * 168 + 64 + cc];
            sh_cb[tid] = cb;
        }
        __syncthreads();

        // 7 j-groups: 6 x 16 + 1 x 4
        #pragma unroll 1
        for (int jg = 0; jg < 7; jg++) {
            const int ng = (jg < 6) ? 16 : 4;
            const int jbase = jg * 16;

            #pragma unroll 4
            for (int jj = 0; jj < ng; jj++) {
                const int j = jbase + jj;
                ULL acc = 0ull;
                const ulonglong2* w2 = (const ulonglong2*)&sh_w[j][0];
                #pragma unroll
                for (int g = 0; g < 16; g++) {
                    ulonglong2 a = w2[g];
                    acc = fma2(a.x, xv[2 * g], acc);
                    acc = fma2(a.y, xv[2 * g + 1], acc);
                }
                sh_t[tid][jj] = hsum2(acc) + sh_cb[j];
            }
            __syncthreads();

            // cooperative coalesced store: consecutive lanes -> consecutive
            // flat (pos, jj) -> 64B-contiguous global segments
            for (int f = tid; f < 256 * ng; f += 256) {
                int pos = f / ng, jj = f - pos * ng;
                dst_base[(size_t)pos * 100 + jbase + jj] = sh_t[pos][jj];
            }
            __syncthreads();  // WAR before next group's sh_t writes
        }
    }
}

// ---------------- K2: sequential scan ---------------------------------------
// 128 blocks x 4 batch rows x 400 threads: thread (j = tid%100, c = tid/100).
// Matvecs: chunk c covers k in [28c, 28c+28) (padded to 112 with zeros).
// Activation/update phases: thread (j,c) owns row r=c -> all threads busy,
// 1 sigmoid + 1 tanh per thread per step, coalesced hidden stores.
__global__ void __launch_bounds__(400, 1)
scan_kernel(const float* __restrict__ Wf_w, const float* __restrict__ Wh_w,
            float* __restrict__ hidden)
{
    const int tid = threadIdx.x;
    const int c = tid / 100;
    const int j = tid - c * 100;
    const int kb = 28 * c;
    const int rbase = blockIdx.x * 4;

    __shared__ __align__(16) float sh_h[4][112];
    __shared__ __align__(16) float sh_fh[4][112];
    __shared__ __align__(16) float sh_p[4][100][4];  // [chunk][j][row]

    // register-resident recurrence weights (k-pair packed), pad pairs = 0
    ULL wf2[14], wh2[14];
    {
        const int lc = (c == 3) ? 8 : 14;  // real pairs in this chunk (k<=99)
        const ULL* pf = (const ULL*)(Wf_w + j * 168 + 68 + kb);
        const ULL* ph = (const ULL*)(Wh_w + j * 168 + 68 + kb);
        #pragma unroll
        for (int t = 0; t < 14; t++) {
            wf2[t] = (t < lc) ? pf[t] : 0ull;
            wh2[t] = (t < lc) ? ph[t] : 0ull;
        }
    }

    // h0 = 0 (also zeroes k=100..111 padding)
    for (int idx = tid; idx < 4 * 112; idx += 400) {
        (&sh_h[0][0])[idx]  = 0.f;
        (&sh_fh[0][0])[idx] = 0.f;
    }
    __syncthreads();

    const int r = c;  // row this thread owns in activation phases
    const size_t xbase = (size_t)(rbase + r) * 51200 + j;
    float xf_cur = g_xf[xbase];
    float xh_cur = g_xh[xbase];
    float xf_nxt = 0.f, xh_nxt = 0.f, fg = 0.f, hold = 0.f;

    #pragma unroll 1
    for (int s = 0; s < 512; s++) {
        // -- matvec 1: Wf_h . h (partial over own chunk, 4 rows)
        {
            ULL a0 = 0ull, a1 = 0ull, a2 = 0ull, a3 = 0ull;
            #pragma unroll
            for (int t = 0; t < 7; t++) {
                ulonglong2 h0 = *(const ulonglong2*)&sh_h[0][kb + 4 * t];
                ulonglong2 h1 = *(const ulonglong2*)&sh_h[1][kb + 4 * t];
                ulonglong2 h2 = *(const ulonglong2*)&sh_h[2][kb + 4 * t];
                ulonglong2 h3 = *(const ulonglong2*)&sh_h[3][kb + 4 * t];
                a0 = fma2(wf2[2 * t], h0.x, a0); a0 = fma2(wf2[2 * t + 1], h0.y, a0);
                a1 = fma2(wf2[2 * t], h1.x, a1); a1 = fma2(wf2[2 * t + 1], h1.y, a1);
                a2 = fma2(wf2[2 * t], h2.x, a2); a2 = fma2(wf2[2 * t + 1], h2.y, a2);
                a3 = fma2(wf2[2 * t], h3.x, a3); a3 = fma2(wf2[2 * t + 1], h3.y, a3);
            }
            *(float4*)&sh_p[c][j][0] =
                make_float4(hsum2(a0), hsum2(a1), hsum2(a2), hsum2(a3));
        }
        __syncthreads();  // (1)

        // -- act 1: f-gate, f*h  (all threads, row r)
        {
            float sum = sh_p[0][j][r] + sh_p[1][j][r] + sh_p[2][j][r] + sh_p[3][j][r];
            fg = sigmoidf_(sum + xf_cur);
            hold = sh_h[r][j];
            sh_fh[r][j] = fg * hold;
            int sp = (s < 511) ? s + 1 : 511;
            xf_nxt = g_xf[xbase + (size_t)sp * 100];
            xh_nxt = g_xh[xbase + (size_t)sp * 100];
        }
        __syncthreads();  // (2)

        // -- matvec 2: Wh_h . (f*h)
        {
            ULL a0 = 0ull, a1 = 0ull, a2 = 0ull, a3 = 0ull;
            #pragma unroll
            for (int t = 0; t < 7; t++) {
                ulonglong2 h0 = *(const ulonglong2*)&sh_fh[0][kb + 4 * t];
                ulonglong2 h1 = *(const ulonglong2*)&sh_fh[1][kb + 4 * t];
                ulonglong2 h2 = *(const ulonglong2*)&sh_fh[2][kb + 4 * t];
                ulonglong2 h3 = *(const ulonglong2*)&sh_fh[3][kb + 4 * t];
                a0 = fma2(wh2[2 * t], h0.x, a0); a0 = fma2(wh2[2 * t + 1], h0.y, a0);
                a1 = fma2(wh2[2 * t], h1.x, a1); a1 = fma2(wh2[2 * t + 1], h1.y, a1);
                a2 = fma2(wh2[2 * t], h2.x, a2); a2 = fma2(wh2[2 * t + 1], h2.y, a2);
                a3 = fma2(wh2[2 * t], h3.x, a3); a3 = fma2(wh2[2 * t + 1], h3.y, a3);
            }
            *(float4*)&sh_p[c][j][0] =
                make_float4(hsum2(a0), hsum2(a1), hsum2(a2), hsum2(a3));
        }
        __syncthreads();  // (3)

        // -- act 2: h update + store (all threads, row r)
        {
            float sum = sh_p[0][j][r] + sh_p[1][j][r] + sh_p[2][j][r] + sh_p[3][j][r];
            float ht = tanhf_(sum + xh_cur);
            float hn = hold + fg * (ht - hold);
            sh_h[r][j] = hn;
            hidden[((size_t)(rbase + r) * 512 + s) * 100 + j] = hn;
            xf_cur = xf_nxt;
            xh_cur = xh_nxt;
        }
        __syncthreads();  // (4)
    }
}

// ---------------- K3: output head -------------------------------------------
__global__ void head_kernel(const float* __restrict__ hidden,
                            const float* __restrict__ ro_w,
                            const float* __restrict__ ro_b,
                            float* __restrict__ out)
{
    int t = blockIdx.x * blockDim.x + threadIdx.x;
    if (t >= 512 * 7) return;
    int b = t / 7, o = t % 7;
    const float* h = hidden + ((size_t)b * 512 + 511) * 100;
    const float* w = ro_w + o * 100;
    float acc = ro_b[o];
    #pragma unroll 4
    for (int k = 0; k < 100; k++) acc += h[k] * w[k];
    out[t] = acc;
}

// ---------------- launch -----------------------------------------------------
extern "C" void kernel_launch(void* const* d_in, const int* in_sizes, int n_in,
                              void* d_out, int out_size)
{
    (void)in_sizes; (void)n_in; (void)out_size;
    const float* x     = (const float*)d_in[0];
    const float* ctx   = (const float*)d_in[1];
    const float* Wf_w  = (const float*)d_in[2];
    const float* Wf_b  = (const float*)d_in[3];
    const float* Wh_w  = (const float*)d_in[4];
    const float* Wh_b  = (const float*)d_in[5];
    const float* ro_w  = (const float*)d_in[6];
    const float* ro_b  = (const float*)d_in[7];

    float* out    = (float*)d_out;
    float* hidden = out + 512 * 7;

    pre_kernel<<<1024, 256>>>(x, ctx, Wf_w, Wf_b, Wh_w, Wh_b);
    scan_kernel<<<128, 400>>>(Wf_w, Wh_w, hidden);
    head_kernel<<<14, 256>>>(hidden, ro_w, ro_b, out);
}